// round 14
// baseline (speedup 1.0000x reference)
#include <cuda_runtime.h>
#include <cuda_bf16.h>
#include <cuda_fp16.h>
#include <math.h>
#include <stdint.h>

#define NI 10000
#define H  128
#define L  50
#define B  64
#define E  160000
#define NC 9999
#define NCP2 10240    // NC padded to 256*40
#define LP 64         // L padded for MMA

// ---------------- persistent device scratch ----------------
__device__ float g_agg[NI * H];
__device__ int   g_mark[NI];
__device__ float g_sg [B * L * H];        // pre-relu
__device__ float g_ao [B * L * 256];      // [ain|aout]
__device__ float g_gates[B * L * 512];    // [r_sum | z_sum | i_n | h_n]
__device__ float g_kv [B * L * 2 * H];
__device__ float g_last[B * H];
__device__ float g_u  [B * H];
__device__ float g_uc [B * NC];
__device__ float g_cTA[NC * 256];         // [cT | cA]
__device__ float g_bc [512];
__device__ float g_bio[256];
// fp16 split operands
__device__ __half g_Ah2[B * L * 384], g_Al2[B * L * 384]; // [inp|h0] for gates GEMM
__device__ __half g_fch[B * L * H], g_fcl[B * L * H];     // final compact
// fp16 split weights
__device__ __half g_gWh[H * H],    g_gWl[H * H];
__device__ __half g_kvwh[256 * H], g_kvwl[256 * H];
__device__ __half g_wcth[256 * H], g_wctl[256 * H];       // [wt | w3^T]
__device__ __half g_Wch[512 * 384], g_Wcl[512 * 384];
__device__ __half g_Wioh[256 * H], g_Wiol[256 * H];
// tail operands
__device__ __half g_fh [B * LP * H];      // zero-padded rows >= L (never written there)
__device__ __half g_fl [B * LP * H];
__device__ __half g_cTh[NCP2 * H];
__device__ __half g_cAh[NCP2 * H];

// ---------------- mma helpers ----------------
__device__ __forceinline__ void ldsm_x4(uint32_t addr, uint32_t& r0, uint32_t& r1,
                                        uint32_t& r2, uint32_t& r3) {
    asm volatile("ldmatrix.sync.aligned.m8n8.x4.shared.b16 {%0,%1,%2,%3}, [%4];"
                 : "=r"(r0), "=r"(r1), "=r"(r2), "=r"(r3) : "r"(addr));
}
__device__ __forceinline__ void mma_fp16(float* d, uint32_t a0, uint32_t a1,
                                         uint32_t a2, uint32_t a3,
                                         uint32_t b0, uint32_t b1) {
    asm volatile(
        "mma.sync.aligned.m16n8k16.row.col.f32.f16.f16.f32 "
        "{%0,%1,%2,%3}, {%4,%5,%6,%7}, {%8,%9}, {%0,%1,%2,%3};"
        : "+f"(d[0]), "+f"(d[1]), "+f"(d[2]), "+f"(d[3])
        : "r"(a0), "r"(a1), "r"(a2), "r"(a3), "r"(b0), "r"(b1));
}
__device__ __forceinline__ uint32_t swz(uint32_t base, int row, int ch, int rs_ch) {
    return base + (uint32_t)(row * rs_ch * 16 + (((ch) ^ (row & 7)) << 4));
}

// ---------------- mark session items ----------------
__global__ void k_mark(const int* __restrict__ items) {
    int i = blockIdx.x * blockDim.x + threadIdx.x;
    if (i < B * L) g_mark[items[i]] = 1;
}

// ---------------- edge scatter ----------------
__global__ void k_edge(const int* __restrict__ row, const int* __restrict__ col,
                       const float* __restrict__ w, const float* __restrict__ emb) {
    int i = blockIdx.x * blockDim.x + threadIdx.x;
    int e = i >> 5;
    int q = i & 31;
    if (e < E) {
        int r = row[e];
        if (g_mark[r]) {
            float ww = w[e];
            int c = col[e];
            float4 v = ((const float4*)(emb + c * H))[q];
            v.x *= ww; v.y *= ww; v.z *= ww; v.w *= ww;
            float* dst = &g_agg[r * H + q * 4];
            asm volatile("red.global.add.v4.f32 [%0], {%1, %2, %3, %4};"
                         :: "l"(dst), "f"(v.x), "f"(v.y), "f"(v.z), "f"(v.w)
                         : "memory");
        }
    }
}

// ---------------- s1 weight prep: wcat = [wt | w3^T] fp16 h/l ----------------
__global__ void k_prep1(const float* __restrict__ wt, const float* __restrict__ w3) {
    int n = blockIdx.x, k = threadIdx.x;   // 256 x 128
    float v = (n < 128) ? wt[n * H + k] : w3[k * 384 + (n - 128)];
    __half h = __float2half(v);
    g_wcth[n * H + k] = h;
    g_wctl[n * H + k] = __float2half(v - __half2float(h));
}

// ---------------- s2 weight prep ----------------
__global__ void k_prep2(const float* __restrict__ liW, const float* __restrict__ lib,
                        const float* __restrict__ loW, const float* __restrict__ lob,
                        const float* __restrict__ w_ih, const float* __restrict__ w_hh,
                        const float* __restrict__ b_ih, const float* __restrict__ b_hh,
                        const float* __restrict__ gW, const float* __restrict__ kvw) {
    int n = blockIdx.x, k = threadIdx.x;   // 1152 x 384
    if (n < 512) {
        int j = n & 127;
        int sec = n >> 7;
        float v;
        if (sec <= 1) {
            int row = sec * 128 + j;
            v = (k < 256) ? w_ih[row * 256 + k] : w_hh[row * 128 + (k - 256)];
        } else if (sec == 2) {
            v = (k < 256) ? w_ih[(256 + j) * 256 + k] : 0.f;
        } else {
            v = (k < 256) ? 0.f : w_hh[(256 + j) * 128 + (k - 256)];
        }
        __half h = __float2half(v);
        g_Wch[n * 384 + k] = h;
        g_Wcl[n * 384 + k] = __float2half(v - __half2float(h));
        if (k == 0) {
            float bb;
            if (sec == 0)      bb = b_ih[j] + b_hh[j];
            else if (sec == 1) bb = b_ih[128 + j] + b_hh[128 + j];
            else if (sec == 2) bb = b_ih[256 + j];
            else               bb = b_hh[256 + j];
            g_bc[n] = bb;
        }
    } else if (n < 768) {
        int m = n - 512;
        if (k < 128) {
            float v = (m < 128) ? liW[m * 128 + k] : loW[(m - 128) * 128 + k];
            __half h = __float2half(v);
            g_Wioh[m * 128 + k] = h;
            g_Wiol[m * 128 + k] = __float2half(v - __half2float(h));
            if (k == 0) g_bio[m] = (m < 128) ? lib[m] : lob[m - 128];
        }
    } else if (n < 896) {
        int m = n - 768;
        if (k < 128) {
            float v = gW[m * H + k];
            __half h = __float2half(v);
            g_gWh[m * H + k] = h;
            g_gWl[m * H + k] = __float2half(v - __half2float(h));
        }
    } else {
        int m = n - 896;
        if (k < 128) {
            float v = kvw[m * H + k];
            __half h = __float2half(v);
            g_kvwh[m * H + k] = h;
            g_kvwl[m * H + k] = __float2half(v - __half2float(h));
        }
    }
}

// ---------------- tensor-core GEMM (3-term compensated) ----------------
#define G16_SMEM 49152
__global__ void __launch_bounds__(256) k_gemm16(
    const void* __restrict__ A, const __half* __restrict__ Al_,
    const __half* __restrict__ Bh, const __half* __restrict__ Bl,
    const float* __restrict__ bias, float* __restrict__ C,
    int M, int N, int K, int a32, const int* __restrict__ aidx) {
    extern __shared__ char smc[];
    uint32_t sb = (uint32_t)__cvta_generic_to_shared(smc);
    const int SA_H = 0, SA_L = 16384, SB_H = 32768, SB_L = 40960;
    int t = threadIdx.x;
    int w = t >> 5, lane = t & 31;
    int mat = lane >> 3, rin = lane & 7;
    int g = lane >> 2, tg = lane & 3;
    int Rm = 16 * w;
    int m0 = blockIdx.y * 128, n0 = blockIdx.x * 64;
    int row_a = Rm + rin + ((mat & 1) << 3);
    int row_b = rin + ((mat >> 1) << 3);

    float acc[8][4] = {};
    for (int k0 = 0; k0 < K; k0 += 64) {
        #pragma unroll
        for (int it = 0; it < 4; it++) {
            int idx = t + 256 * it;
            int r = idx >> 3, c = idx & 7;
            int gm = m0 + r;
            uint4 vh = make_uint4(0, 0, 0, 0), vl = vh;
            if (gm < M) {
                int am = aidx ? aidx[gm] : gm;
                if (a32) {
                    const float* Af = (const float*)A + (size_t)am * K + k0 + c * 8;
                    float4 v0 = *(const float4*)Af;
                    float4 v1 = *(const float4*)(Af + 4);
                    float vs[8] = { v0.x, v0.y, v0.z, v0.w, v1.x, v1.y, v1.z, v1.w };
                    __half hh[8], ll[8];
                    #pragma unroll
                    for (int q = 0; q < 8; q++) {
                        hh[q] = __float2half(vs[q]);
                        ll[q] = __float2half(vs[q] - __half2float(hh[q]));
                    }
                    vh = *(uint4*)hh;
                    vl = *(uint4*)ll;
                } else {
                    vh = *(const uint4*)&((const __half*)A)[(size_t)am * K + k0 + c * 8];
                    vl = *(const uint4*)&Al_[(size_t)am * K + k0 + c * 8];
                }
            }
            uint32_t off = (uint32_t)(r * 128 + ((c ^ (r & 7)) << 4));
            *(uint4*)(smc + SA_H + off) = vh;
            *(uint4*)(smc + SA_L + off) = vl;
        }
        #pragma unroll
        for (int it = 0; it < 2; it++) {
            int idx = t + 256 * it;
            int r = idx >> 3, c = idx & 7;
            int gn = n0 + r;
            uint4 vh = make_uint4(0, 0, 0, 0), vl = vh;
            if (gn < N) {
                vh = *(const uint4*)&Bh[gn * K + k0 + c * 8];
                vl = *(const uint4*)&Bl[gn * K + k0 + c * 8];
            }
            uint32_t off = (uint32_t)(r * 128 + ((c ^ (r & 7)) << 4));
            *(uint4*)(smc + SB_H + off) = vh;
            *(uint4*)(smc + SB_L + off) = vl;
        }
        __syncthreads();
        #pragma unroll
        for (int k16 = 0; k16 < 4; k16++) {
            uint32_t aH[4], aL[4];
            int ca = 2 * k16 + (mat >> 1);
            ldsm_x4(swz(sb + SA_H, row_a, ca, 8), aH[0], aH[1], aH[2], aH[3]);
            ldsm_x4(swz(sb + SA_L, row_a, ca, 8), aL[0], aL[1], aL[2], aL[3]);
            int cb = 2 * k16 + (mat & 1);
            uint32_t bH[4][4], bL[4][4];
            #pragma unroll
            for (int nh = 0; nh < 4; nh++) {
                ldsm_x4(swz(sb + SB_H, 16 * nh + row_b, cb, 8),
                        bH[nh][0], bH[nh][1], bH[nh][2], bH[nh][3]);
                ldsm_x4(swz(sb + SB_L, 16 * nh + row_b, cb, 8),
                        bL[nh][0], bL[nh][1], bL[nh][2], bL[nh][3]);
            }
            #pragma unroll
            for (int j = 0; j < 8; j++) {
                uint32_t h0 = bH[j >> 1][2 * (j & 1)], h1 = bH[j >> 1][2 * (j & 1) + 1];
                uint32_t l0 = bL[j >> 1][2 * (j & 1)], l1 = bL[j >> 1][2 * (j & 1) + 1];
                mma_fp16(acc[j], aH[0], aH[1], aH[2], aH[3], h0, h1);
                mma_fp16(acc[j], aL[0], aL[1], aL[2], aL[3], h0, h1);
                mma_fp16(acc[j], aH[0], aH[1], aH[2], aH[3], l0, l1);
            }
        }
        __syncthreads();
    }
    #pragma unroll
    for (int j = 0; j < 8; j++) {
        int gn = n0 + 8 * j + 2 * tg;
        if (gn < N) {
            float b0 = bias ? bias[gn] : 0.f;
            float b1 = bias ? bias[gn + 1] : 0.f;
            int gm0 = m0 + Rm + g;
            if (gm0 < M)
                *(float2*)&C[(size_t)gm0 * N + gn] = make_float2(acc[j][0] + b0, acc[j][1] + b1);
            if (gm0 + 8 < M)
                *(float2*)&C[(size_t)(gm0 + 8) * N + gn] = make_float2(acc[j][2] + b0, acc[j][3] + b1);
        }
    }
}

// ---------------- scalar GEMM (uc only) ----------------
__global__ void __launch_bounds__(256) k_gemm(const float* __restrict__ A,
                                              const float* __restrict__ Bw,
                                              float* __restrict__ C,
                                              int M, int N, int K) {
    __shared__ float As[64][33];
    __shared__ float Bs[64][33];
    int m0 = blockIdx.y * 64, n0 = blockIdx.x * 64;
    int tid = threadIdx.x;
    int tx = tid & 15, ty = tid >> 4;
    float acc[4][4] = {};
    for (int k0 = 0; k0 < K; k0 += 32) {
        #pragma unroll
        for (int i = 0; i < 2; i++) {
            int f = tid + 256 * i;
            int m = f >> 3, k4 = f & 7;
            int gm = m0 + m;
            float4 v = make_float4(0.f, 0.f, 0.f, 0.f);
            if (gm < M) v = *(const float4*)&A[gm * K + k0 + k4 * 4];
            As[m][k4 * 4 + 0] = v.x; As[m][k4 * 4 + 1] = v.y;
            As[m][k4 * 4 + 2] = v.z; As[m][k4 * 4 + 3] = v.w;
        }
        #pragma unroll
        for (int i = 0; i < 2; i++) {
            int f = tid + 256 * i;
            int n = f >> 3, k4 = f & 7;
            int gn = n0 + n;
            float4 v = make_float4(0.f, 0.f, 0.f, 0.f);
            if (gn < N) v = *(const float4*)&Bw[gn * K + k0 + k4 * 4];
            Bs[n][k4 * 4 + 0] = v.x; Bs[n][k4 * 4 + 1] = v.y;
            Bs[n][k4 * 4 + 2] = v.z; Bs[n][k4 * 4 + 3] = v.w;
        }
        __syncthreads();
        #pragma unroll
        for (int k = 0; k < 32; k++) {
            float a[4], b[4];
            #pragma unroll
            for (int r = 0; r < 4; r++) a[r] = As[ty * 4 + r][k];
            #pragma unroll
            for (int c = 0; c < 4; c++) b[c] = Bs[tx * 4 + c][k];
            #pragma unroll
            for (int r = 0; r < 4; r++)
                #pragma unroll
                for (int c = 0; c < 4; c++)
                    acc[r][c] += a[r] * b[c];
        }
        __syncthreads();
    }
    #pragma unroll
    for (int r = 0; r < 4; r++) {
        int gm = m0 + ty * 4 + r;
        if (gm < M) {
            #pragma unroll
            for (int c = 0; c < 4; c++) {
                int gn = n0 + tx * 4 + c;
                if (gn < N) C[gm * N + gn] = acc[r][c];
            }
        }
    }
}

// ---------------- final add ----------------
__global__ void k_add(float* __restrict__ out) {
    int i = blockIdx.x * blockDim.x + threadIdx.x;
    if (i < B * NC) out[i] += g_uc[i];
}

// ---------------- prop: inp = adj @ ao; writes fp16 [inp|h0] operand ----------------
#define PROP_SMEM ((L * L + L * 256) * 4)
__global__ void k_prop(const float* __restrict__ adj, const int* __restrict__ items,
                       const float* __restrict__ emb) {
    extern __shared__ float psm[];
    float* sA  = psm;
    float* sin = psm + L * L;
    int b = blockIdx.x, t = threadIdx.x;
    for (int i = t; i < L * L; i += 256) sA[i] = adj[b * L * L + i];
    for (int k = 0; k < L; k++) sin[k * 256 + t] = g_ao[(b * L + k) * 256 + t];
    __syncthreads();
    for (int l = 0; l < L; l++) {
        float acc = 0.f;
        #pragma unroll 10
        for (int k = 0; k < L; k++)
            acc += sA[l * L + k] * sin[k * 256 + t];
        __half h = __float2half(acc);
        g_Ah2[(b * L + l) * 384 + t] = h;
        g_Al2[(b * L + l) * 384 + t] = __float2half(acc - __half2float(h));
    }
    for (int i = t; i < L * H; i += 256) {
        int l = i >> 7, tt = i & 127;
        float v = emb[items[b * L + l] * H + tt];
        __half h = __float2half(v);
        g_Ah2[(b * L + l) * 384 + 256 + tt] = h;
        g_Al2[(b * L + l) * 384 + 256 + tt] = __float2half(v - __half2float(h));
    }
}

// ---------------- GRU elementwise + final fp16 splits ----------------
__global__ void k_gru_elem(const int* __restrict__ items, const int* __restrict__ lens,
                           const float* __restrict__ pos_emb) {
    int i = blockIdx.x * blockDim.x + threadIdx.x;
    int bl = i >> 7, t = i & 127;
    int b = bl / L, l = bl % L;
    const float* g = g_gates + bl * 512;
    float r = 1.f / (1.f + expf(-g[t]));
    float z = 1.f / (1.f + expf(-g[128 + t]));
    float n = tanhf(g[256 + t] + r * g[384 + t]);
    float h0 = __half2float(g_Ah2[bl * 384 + 256 + t]) + __half2float(g_Al2[bl * 384 + 256 + t]);
    float hn = n + z * (h0 - n);
    int item = items[bl];
    int len  = lens[b];
    int rev  = (item == 0) ? 0 : (len - 1 - l);
    float fin = fmaxf(g_sg[i], 0.f) + hn + pos_emb[rev * H + t];
    __half fh = __float2half(fin);
    __half fl = __float2half(fin - __half2float(fh));
    g_fh[(b * LP + l) * H + t] = fh;
    g_fl[(b * LP + l) * H + t] = fl;
    g_fch[i] = fh;
    g_fcl[i] = fl;
    if (l == len - 1) g_last[b * H + t] = fin;
}

// ---------------- candidate fp16 convert for tail ----------------
__global__ void k_cvt_cand() {
    int i = blockIdx.x * blockDim.x + threadIdx.x;   // NCP2*H
    int n = i >> 7, k = i & 127;
    float vT = 0.f, vA = 0.f;
    if (n < NC) { vT = g_cTA[n * 256 + k]; vA = g_cTA[n * 256 + 128 + k]; }
    g_cTh[i] = __float2half(vT);
    g_cAh[i] = __float2half(vA);
}

// ---------------- attention readout -> g_u ----------------
#define ATTN_SMEM ((L * 2 * H + H + 8 * 64 + 3 * H) * 4 + 64 * 4)
__global__ void k_attn(const int* __restrict__ items,
                       const float* __restrict__ ipw, const float* __restrict__ ipb,
                       const float* __restrict__ opw, const float* __restrict__ opb,
                       const float* __restrict__ w3) {
    extern __shared__ float sm[];
    float* kvs = sm;
    float* qs  = kvs + L * 2 * H;
    float* att = qs + H;
    float* ctx = att + 8 * 64;
    float* sg  = ctx + H;
    float* ls  = sg + H;
    int*   its = (int*)(ls + H);

    int b = blockIdx.x, t = threadIdx.x;
    for (int i = t; i < L * 2 * H; i += 256) kvs[i] = g_kv[b * L * 2 * H + i];
    if (t < H) ls[t] = g_last[b * H + t];
    if (t < L) its[t] = items[b * L + t];
    __syncthreads();

    if (t < H) {
        float a = ipb[t];
        const float* w = ipw + t * H;
        #pragma unroll 8
        for (int k = 0; k < H; k++) a += ls[k] * w[k];
        qs[t] = a;
    }
    __syncthreads();
    for (int i = t; i < 8 * L; i += 256) {
        int hd = i / L, l = i % L;
        float a = 0.f;
        #pragma unroll
        for (int d = 0; d < 16; d++) a += qs[hd * 16 + d] * kvs[l * 2 * H + hd * 16 + d];
        att[hd * 64 + l] = (its[l] == 0) ? -INFINITY : a * 0.25f;
    }
    __syncthreads();
    if (t < 8) {
        float m = -INFINITY;
        for (int l = 0; l < L; l++) m = fmaxf(m, att[t * 64 + l]);
        float s = 0.f;
        for (int l = 0; l < L; l++) {
            float e = expf(att[t * 64 + l] - m);
            att[t * 64 + l] = e;
            s += e;
        }
        float inv = 1.f / s;
        for (int l = 0; l < L; l++) att[t * 64 + l] *= inv;
    }
    __syncthreads();
    if (t < H) {
        int hd = t / 16;
        float c = 0.f;
        for (int l = 0; l < L; l++) c += att[hd * 64 + l] * kvs[l * 2 * H + H + t];
        ctx[t] = c;
    }
    __syncthreads();
    if (t < H) {
        float a = opb[t];
        const float* w = opw + t * H;
        #pragma unroll 8
        for (int k = 0; k < H; k++) a += ctx[k] * w[k];
        sg[t] = a;
    }
    __syncthreads();
    if (t < H) {
        float u = 0.f;
        const float* w1 = w3 + t * 3 * H + H;
        const float* w2 = w3 + t * 3 * H + 2 * H;
        #pragma unroll 8
        for (int k = 0; k < H; k++) u += ls[k] * w1[k] + sg[k] * w2[k];
        g_u[b * H + t] = u;
    }
}

// ---------------- tensor-core tail: 256-cand CTA tile, 32 cands/warp ----------------
// smem: cT[256x128 fp16]=64K | cA=64K | F=[fh|fl][64x256 fp16]=32K | its
#define T_CT  0
#define T_CA  65536
#define T_F   131072
#define T_ITS 163840
#define TAIL_SMEM (T_ITS + 256)

__global__ void __launch_bounds__(256, 1) k_tail(const int* __restrict__ items,
                                                 float* __restrict__ out) {
    extern __shared__ char smc[];
    uint32_t sb = (uint32_t)__cvta_generic_to_shared(smc);
    int*   its = (int*)(smc + T_ITS);

    int n0 = blockIdx.x * 256;
    int bg = blockIdx.y * 8;
    int t  = threadIdx.x;
    int w  = t >> 5, lane = t & 31;
    int mat = lane >> 3, rin = lane & 7;
    int g = lane >> 2, tg = lane & 3;
    int Rm = 32 * w;                          // warp owns 32 candidate rows

    // ---- load candidate tiles (256 rows x 16 chunks each) ----
    #pragma unroll
    for (int it = 0; it < 16; it++) {
        int idx = t + 256 * it;
        int r = idx >> 4, c = idx & 15;
        uint4 v = *(const uint4*)&g_cTh[(n0 + r) * H + c * 8];
        *(uint4*)(smc + T_CT + r * 256 + ((c ^ (r & 7)) << 4)) = v;
    }
    #pragma unroll
    for (int it = 0; it < 16; it++) {
        int idx = t + 256 * it;
        int r = idx >> 4, c = idx & 15;
        uint4 v = *(const uint4*)&g_cAh[(n0 + r) * H + c * 8];
        *(uint4*)(smc + T_CA + r * 256 + ((c ^ (r & 7)) << 4)) = v;
    }

    for (int bi = 0; bi < 8; bi++) {
        int b = bg + bi;
        #pragma unroll
        for (int it = 0; it < 8; it++) {
            int idx = t + 256 * it;
            int r = idx >> 5, c = idx & 31;
            const __half* src = (c < 16) ? &g_fh[(b * LP + r) * H + c * 8]
                                         : &g_fl[(b * LP + r) * H + (c - 16) * 8];
            uint4 v = *(const uint4*)src;
            *(uint4*)(smc + T_F + r * 512 + ((c ^ (r & 7)) << 4)) = v;
        }
        if (t < 64) its[t] = (t < L) ? items[b * L + t] : 0;
        __syncthreads();

        float Sacc[2][8][4] = {}, Gacc[2][8][4] = {};
        for (int kc = 0; kc < 8; kc++) {
            uint32_t aT[2][4], aA[2][4];
            int ch_a = 2 * kc + (mat >> 1);
            #pragma unroll
            for (int mi = 0; mi < 2; mi++) {
                int row_a = Rm + 16 * mi + rin + ((mat & 1) << 3);
                ldsm_x4(swz(sb + T_CT, row_a, ch_a, 16), aT[mi][0], aT[mi][1], aT[mi][2], aT[mi][3]);
                ldsm_x4(swz(sb + T_CA, row_a, ch_a, 16), aA[mi][0], aA[mi][1], aA[mi][2], aA[mi][3]);
            }
            int row_b = rin + ((mat >> 1) << 3);
            uint32_t bf[4][4];
            // fh half -> S and G
            #pragma unroll
            for (int nh = 0; nh < 4; nh++)
                ldsm_x4(swz(sb + T_F, 16 * nh + row_b, 2 * kc + (mat & 1), 32),
                        bf[nh][0], bf[nh][1], bf[nh][2], bf[nh][3]);
            #pragma unroll
            for (int mi = 0; mi < 2; mi++)
                #pragma unroll
                for (int j = 0; j < 8; j++) {
                    uint32_t b0 = bf[j >> 1][2 * (j & 1)], b1 = bf[j >> 1][2 * (j & 1) + 1];
                    mma_fp16(Sacc[mi][j], aT[mi][0], aT[mi][1], aT[mi][2], aT[mi][3], b0, b1);
                    mma_fp16(Gacc[mi][j], aA[mi][0], aA[mi][1], aA[mi][2], aA[mi][3], b0, b1);
                }
            // fl half -> G only
            #pragma unroll
            for (int nh = 0; nh < 4; nh++)
                ldsm_x4(swz(sb + T_F, 16 * nh + row_b, 16 + 2 * kc + (mat & 1), 32),
                        bf[nh][0], bf[nh][1], bf[nh][2], bf[nh][3]);
            #pragma unroll
            for (int mi = 0; mi < 2; mi++)
                #pragma unroll
                for (int j = 0; j < 8; j++) {
                    uint32_t b0 = bf[j >> 1][2 * (j & 1)], b1 = bf[j >> 1][2 * (j & 1) + 1];
                    mma_fp16(Gacc[mi][j], aA[mi][0], aA[mi][1], aA[mi][2], aA[mi][3], b0, b1);
                }
        }

        unsigned mk0 = 0, mk1 = 0;
        #pragma unroll
        for (int j = 0; j < 8; j++) {
            if (its[8 * j + 2 * tg] != 0)     mk0 |= (1u << j);
            if (its[8 * j + 2 * tg + 1] != 0) mk1 |= (1u << j);
        }
        #pragma unroll
        for (int mi = 0; mi < 2; mi++)
            #pragma unroll
            for (int h = 0; h < 2; h++) {
                float m = -INFINITY;
                #pragma unroll
                for (int j = 0; j < 8; j++) {
                    if (mk0 & (1u << j)) m = fmaxf(m, Sacc[mi][j][2 * h]);
                    if (mk1 & (1u << j)) m = fmaxf(m, Sacc[mi][j][2 * h + 1]);
                }
                m = fmaxf(m, __shfl_xor_sync(0xFFFFFFFF, m, 1));
                m = fmaxf(m, __shfl_xor_sync(0xFFFFFFFF, m, 2));
                float s = 0.f, acc = 0.f;
                #pragma unroll
                for (int j = 0; j < 8; j++) {
                    if (mk0 & (1u << j)) {
                        float e = __expf(Sacc[mi][j][2 * h] - m);
                        s += e; acc += e * Gacc[mi][j][2 * h];
                    }
                    if (mk1 & (1u << j)) {
                        float e = __expf(Sacc[mi][j][2 * h + 1] - m);
                        s += e; acc += e * Gacc[mi][j][2 * h + 1];
                    }
                }
                s   += __shfl_xor_sync(0xFFFFFFFF, s, 1);
                s   += __shfl_xor_sync(0xFFFFFFFF, s, 2);
                acc += __shfl_xor_sync(0xFFFFFFFF, acc, 1);
                acc += __shfl_xor_sync(0xFFFFFFFF, acc, 2);
                if (tg == 0) {
                    int gn = n0 + Rm + 16 * mi + g + 8 * h;
                    if (gn < NC) out[b * NC + gn] = acc / s;
                }
            }
        __syncthreads();
    }
}

// ---------------- host launcher ----------------
extern "C" void kernel_launch(void* const* d_in, const int* in_sizes, int n_in,
                              void* d_out, int out_size) {
    const int*   items = (const int*)d_in[0];
    const int*   lens  = (const int*)d_in[1];
    const float* adj   = (const float*)d_in[2];
    const int*   erow  = (const int*)d_in[3];
    const int*   ecol  = (const int*)d_in[4];
    const float* ew    = (const float*)d_in[5];
    const float* emb   = (const float*)d_in[6];
    const float* pos   = (const float*)d_in[7];
    const float* gW    = (const float*)d_in[8];
    const float* gb    = (const float*)d_in[9];
    const float* liW   = (const float*)d_in[10];
    const float* lib   = (const float*)d_in[11];
    const float* loW   = (const float*)d_in[12];
    const float* lob   = (const float*)d_in[13];
    const float* w_ih  = (const float*)d_in[14];
    const float* w_hh  = (const float*)d_in[15];
    const float* b_ih  = (const float*)d_in[16];
    const float* b_hh  = (const float*)d_in[17];
    const float* ipw   = (const float*)d_in[18];
    const float* ipb   = (const float*)d_in[19];
    const float* opw   = (const float*)d_in[20];
    const float* opb   = (const float*)d_in[21];
    const float* wt    = (const float*)d_in[22];
    const float* w3    = (const float*)d_in[23];
    float* out = (float*)d_out;

    static bool s_init = false;
    static cudaStream_t s1, s2, s3;
    static cudaEvent_t evRoot, evCand, evGru, evGE, evUC, evPrep;
    if (!s_init) {
        cudaStreamCreateWithFlags(&s1, cudaStreamNonBlocking);
        cudaStreamCreateWithFlags(&s2, cudaStreamNonBlocking);
        cudaStreamCreateWithFlags(&s3, cudaStreamNonBlocking);
        cudaEventCreateWithFlags(&evRoot, cudaEventDisableTiming);
        cudaEventCreateWithFlags(&evCand, cudaEventDisableTiming);
        cudaEventCreateWithFlags(&evGru,  cudaEventDisableTiming);
        cudaEventCreateWithFlags(&evGE,   cudaEventDisableTiming);
        cudaEventCreateWithFlags(&evUC,   cudaEventDisableTiming);
        cudaEventCreateWithFlags(&evPrep, cudaEventDisableTiming);
        cudaFuncSetAttribute(k_attn, cudaFuncAttributeMaxDynamicSharedMemorySize, ATTN_SMEM);
        cudaFuncSetAttribute(k_tail, cudaFuncAttributeMaxDynamicSharedMemorySize, TAIL_SMEM);
        cudaFuncSetAttribute(k_prop, cudaFuncAttributeMaxDynamicSharedMemorySize, PROP_SMEM);
        cudaFuncSetAttribute(k_gemm16, cudaFuncAttributeMaxDynamicSharedMemorySize, G16_SMEM);
        s_init = true;
    }

    float* p_agg;   cudaGetSymbolAddress((void**)&p_agg,   g_agg);
    int*   p_mark;  cudaGetSymbolAddress((void**)&p_mark,  g_mark);
    float* p_sg;    cudaGetSymbolAddress((void**)&p_sg,    g_sg);
    float* p_ao;    cudaGetSymbolAddress((void**)&p_ao,    g_ao);
    float* p_gates; cudaGetSymbolAddress((void**)&p_gates, g_gates);
    float* p_kv;    cudaGetSymbolAddress((void**)&p_kv,    g_kv);
    float* p_u;     cudaGetSymbolAddress((void**)&p_u,     g_u);
    float* p_uc;    cudaGetSymbolAddress((void**)&p_uc,    g_uc);
    float* p_cTA;   cudaGetSymbolAddress((void**)&p_cTA,   g_cTA);
    float* p_bc;    cudaGetSymbolAddress((void**)&p_bc,    g_bc);
    float* p_bio;   cudaGetSymbolAddress((void**)&p_bio,   g_bio);
    __half *p_Ah2, *p_Al2, *p_fch, *p_fcl;
    __half *p_gWh, *p_gWl, *p_kvwh, *p_kvwl, *p_wcth, *p_wctl;
    __half *p_Wch, *p_Wcl, *p_Wioh, *p_Wiol;
    cudaGetSymbolAddress((void**)&p_Ah2, g_Ah2);   cudaGetSymbolAddress((void**)&p_Al2, g_Al2);
    cudaGetSymbolAddress((void**)&p_fch, g_fch);   cudaGetSymbolAddress((void**)&p_fcl, g_fcl);
    cudaGetSymbolAddress((void**)&p_gWh, g_gWh);   cudaGetSymbolAddress((void**)&p_gWl, g_gWl);
    cudaGetSymbolAddress((void**)&p_kvwh, g_kvwh); cudaGetSymbolAddress((void**)&p_kvwl, g_kvwl);
    cudaGetSymbolAddress((void**)&p_wcth, g_wcth); cudaGetSymbolAddress((void**)&p_wctl, g_wctl);
    cudaGetSymbolAddress((void**)&p_Wch, g_Wch);   cudaGetSymbolAddress((void**)&p_Wcl, g_Wcl);
    cudaGetSymbolAddress((void**)&p_Wioh, g_Wioh); cudaGetSymbolAddress((void**)&p_Wiol, g_Wiol);

    const int M = B * L;   // 3200

    cudaEventRecord(evRoot, 0);
    cudaStreamWaitEvent(s1, evRoot, 0);
    cudaStreamWaitEvent(s2, evRoot, 0);

    // ---- s1: candidate chain ----
    k_prep1<<<256, 128, 0, s1>>>(wt, w3);
    k_gemm16<<<dim3(4, (NC + 127) / 128), 256, G16_SMEM, s1>>>(
        emb + H, nullptr, p_wcth, p_wctl, (const float*)nullptr, p_cTA,
        NC, 256, H, 1, nullptr);
    k_cvt_cand<<<(NCP2 * H) / 256, 256, 0, s1>>>();
    cudaEventRecord(evCand, s1);

    // ---- s2: GRU chain ----
    k_prep2<<<1152, 384, 0, s2>>>(liW, lib, loW, lob, w_ih, w_hh, b_ih, b_hh,
                                  gW, ipw + H * H);
    cudaEventRecord(evPrep, s2);
    k_gemm16<<<dim3(4, 25), 256, G16_SMEM, s2>>>(
        emb, nullptr, p_Wioh, p_Wiol, p_bio, p_ao, M, 256, H, 1, items);
    k_prop<<<B, 256, PROP_SMEM, s2>>>(adj, items, emb);
    k_gemm16<<<dim3(8, 25), 256, G16_SMEM, s2>>>(
        p_Ah2, p_Al2, p_Wch, p_Wcl, p_bc, p_gates, M, 512, 384, 0, nullptr);
    cudaEventRecord(evGru, s2);

    // ---- s0: edge scatter + sg ----
    cudaMemsetAsync(p_agg, 0, NI * H * sizeof(float));
    cudaMemsetAsync(p_mark, 0, NI * sizeof(int));
    k_mark<<<(B * L + 255) / 256, 256>>>(items);
    k_edge<<<(E * 32 + 255) / 256, 256>>>(erow, ecol, ew, emb);
    cudaStreamWaitEvent(0, evPrep, 0);
    k_gemm16<<<dim3(2, 25), 256, G16_SMEM>>>(
        p_agg, nullptr, p_gWh, p_gWl, gb, p_sg, M, H, H, 1, items);

    cudaStreamWaitEvent(0, evGru, 0);
    k_gru_elem<<<(M * H) / 256, 256>>>(items, lens, pos);
    cudaEventRecord(evGE, 0);

    // ---- s3: attention branch + uc (concurrent with tail) ----
    cudaStreamWaitEvent(s3, evGE, 0);
    k_gemm16<<<dim3(4, 25), 256, G16_SMEM, s3>>>(
        p_fch, p_fcl, p_kvwh, p_kvwl, ipb + H, p_kv, M, 256, H, 0, nullptr);
    k_attn<<<B, 256, ATTN_SMEM, s3>>>(items, ipw, ipb, opw, opb, w3);
    k_gemm<<<dim3((NC + 63) / 64, 1), 256, 0, s3>>>(p_u, emb + H, p_uc, B, NC, H);
    cudaEventRecord(evUC, s3);

    // ---- s0: tail, then add ----
    cudaStreamWaitEvent(0, evCand, 0);
    k_tail<<<dim3(NCP2 / 256, B / 8), 256, TAIL_SMEM>>>(items, out);

    cudaStreamWaitEvent(0, evUC, 0);
    k_add<<<(B * NC + 255) / 256, 256>>>(out);
}

// round 15
// speedup vs baseline: 1.4996x; 1.4996x over previous
#include <cuda_runtime.h>
#include <cuda_bf16.h>
#include <cuda_fp16.h>
#include <math.h>
#include <stdint.h>

#define NI 10000
#define H  128
#define L  50
#define B  64
#define E  160000
#define NC 9999
#define NCP 10112     // NC padded to 64*158
#define LP 64         // L padded for MMA

// ---------------- persistent device scratch ----------------
__device__ float g_agg[NI * H];
__device__ int   g_mark[NI];
__device__ float g_sg [B * L * H];        // pre-relu
__device__ float g_ao [B * L * 256];      // [ain|aout]
__device__ float g_gates[B * L * 512];    // [r_sum | z_sum | i_n | h_n]
__device__ float g_kv [B * L * 2 * H];
__device__ float g_last[B * H];
__device__ float g_u  [B * H];
__device__ float g_uc [B * NC];
__device__ float g_cTA[NC * 256];         // [cT | cA]
__device__ float g_bc [512];
__device__ float g_bio[256];
// fp16 split operands
__device__ __half g_Ah2[B * L * 384], g_Al2[B * L * 384]; // [inp|h0] for gates GEMM
__device__ __half g_fch[B * L * H], g_fcl[B * L * H];     // final compact
// fp16 split weights
__device__ __half g_gWh[H * H],    g_gWl[H * H];
__device__ __half g_kvwh[256 * H], g_kvwl[256 * H];
__device__ __half g_wcth[256 * H], g_wctl[256 * H];       // [wt | w3^T]
__device__ __half g_Wch[512 * 384], g_Wcl[512 * 384];
__device__ __half g_Wioh[256 * H], g_Wiol[256 * H];
// tail operands
__device__ __half g_fh [B * LP * H];      // zero-padded rows >= L (never written there)
__device__ __half g_fl [B * LP * H];
__device__ __half g_cTh[NCP * H];
__device__ __half g_cAh[NCP * H];

// ---------------- mma helpers ----------------
__device__ __forceinline__ void ldsm_x4(uint32_t addr, uint32_t& r0, uint32_t& r1,
                                        uint32_t& r2, uint32_t& r3) {
    asm volatile("ldmatrix.sync.aligned.m8n8.x4.shared.b16 {%0,%1,%2,%3}, [%4];"
                 : "=r"(r0), "=r"(r1), "=r"(r2), "=r"(r3) : "r"(addr));
}
__device__ __forceinline__ void mma_fp16(float* d, uint32_t a0, uint32_t a1,
                                         uint32_t a2, uint32_t a3,
                                         uint32_t b0, uint32_t b1) {
    asm volatile(
        "mma.sync.aligned.m16n8k16.row.col.f32.f16.f16.f32 "
        "{%0,%1,%2,%3}, {%4,%5,%6,%7}, {%8,%9}, {%0,%1,%2,%3};"
        : "+f"(d[0]), "+f"(d[1]), "+f"(d[2]), "+f"(d[3])
        : "r"(a0), "r"(a1), "r"(a2), "r"(a3), "r"(b0), "r"(b1));
}
__device__ __forceinline__ uint32_t swz(uint32_t base, int row, int ch, int rs_ch) {
    return base + (uint32_t)(row * rs_ch * 16 + (((ch) ^ (row & 7)) << 4));
}

// ---------------- mark session items ----------------
__global__ void k_mark(const int* __restrict__ items) {
    int i = blockIdx.x * blockDim.x + threadIdx.x;
    if (i < B * L) g_mark[items[i]] = 1;
}

// ---------------- edge scatter ----------------
__global__ void k_edge(const int* __restrict__ row, const int* __restrict__ col,
                       const float* __restrict__ w, const float* __restrict__ emb) {
    int i = blockIdx.x * blockDim.x + threadIdx.x;
    int e = i >> 5;
    int q = i & 31;
    if (e < E) {
        int r = row[e];
        if (g_mark[r]) {
            float ww = w[e];
            int c = col[e];
            float4 v = ((const float4*)(emb + c * H))[q];
            v.x *= ww; v.y *= ww; v.z *= ww; v.w *= ww;
            float* dst = &g_agg[r * H + q * 4];
            asm volatile("red.global.add.v4.f32 [%0], {%1, %2, %3, %4};"
                         :: "l"(dst), "f"(v.x), "f"(v.y), "f"(v.z), "f"(v.w)
                         : "memory");
        }
    }
}

// ---------------- s1 weight prep: wcat = [wt | w3^T] fp16 h/l ----------------
__global__ void k_prep1(const float* __restrict__ wt, const float* __restrict__ w3) {
    int n = blockIdx.x, k = threadIdx.x;   // 256 x 128
    float v = (n < 128) ? wt[n * H + k] : w3[k * 384 + (n - 128)];
    __half h = __float2half(v);
    g_wcth[n * H + k] = h;
    g_wctl[n * H + k] = __float2half(v - __half2float(h));
}

// ---------------- s2 weight prep ----------------
__global__ void k_prep2(const float* __restrict__ liW, const float* __restrict__ lib,
                        const float* __restrict__ loW, const float* __restrict__ lob,
                        const float* __restrict__ w_ih, const float* __restrict__ w_hh,
                        const float* __restrict__ b_ih, const float* __restrict__ b_hh,
                        const float* __restrict__ gW, const float* __restrict__ kvw) {
    int n = blockIdx.x, k = threadIdx.x;   // 1152 x 384
    if (n < 512) {
        int j = n & 127;
        int sec = n >> 7;
        float v;
        if (sec <= 1) {
            int row = sec * 128 + j;
            v = (k < 256) ? w_ih[row * 256 + k] : w_hh[row * 128 + (k - 256)];
        } else if (sec == 2) {
            v = (k < 256) ? w_ih[(256 + j) * 256 + k] : 0.f;
        } else {
            v = (k < 256) ? 0.f : w_hh[(256 + j) * 128 + (k - 256)];
        }
        __half h = __float2half(v);
        g_Wch[n * 384 + k] = h;
        g_Wcl[n * 384 + k] = __float2half(v - __half2float(h));
        if (k == 0) {
            float bb;
            if (sec == 0)      bb = b_ih[j] + b_hh[j];
            else if (sec == 1) bb = b_ih[128 + j] + b_hh[128 + j];
            else if (sec == 2) bb = b_ih[256 + j];
            else               bb = b_hh[256 + j];
            g_bc[n] = bb;
        }
    } else if (n < 768) {
        int m = n - 512;
        if (k < 128) {
            float v = (m < 128) ? liW[m * 128 + k] : loW[(m - 128) * 128 + k];
            __half h = __float2half(v);
            g_Wioh[m * 128 + k] = h;
            g_Wiol[m * 128 + k] = __float2half(v - __half2float(h));
            if (k == 0) g_bio[m] = (m < 128) ? lib[m] : lob[m - 128];
        }
    } else if (n < 896) {
        int m = n - 768;
        if (k < 128) {
            float v = gW[m * H + k];
            __half h = __float2half(v);
            g_gWh[m * H + k] = h;
            g_gWl[m * H + k] = __float2half(v - __half2float(h));
        }
    } else {
        int m = n - 896;
        if (k < 128) {
            float v = kvw[m * H + k];
            __half h = __float2half(v);
            g_kvwh[m * H + k] = h;
            g_kvwl[m * H + k] = __float2half(v - __half2float(h));
        }
    }
}

// ---------------- tensor-core GEMM (3-term compensated) ----------------
#define G16_SMEM 49152
__global__ void __launch_bounds__(256) k_gemm16(
    const void* __restrict__ A, const __half* __restrict__ Al_,
    const __half* __restrict__ Bh, const __half* __restrict__ Bl,
    const float* __restrict__ bias, float* __restrict__ C,
    int M, int N, int K, int a32, const int* __restrict__ aidx) {
    extern __shared__ char smc[];
    uint32_t sb = (uint32_t)__cvta_generic_to_shared(smc);
    const int SA_H = 0, SA_L = 16384, SB_H = 32768, SB_L = 40960;
    int t = threadIdx.x;
    int w = t >> 5, lane = t & 31;
    int mat = lane >> 3, rin = lane & 7;
    int g = lane >> 2, tg = lane & 3;
    int Rm = 16 * w;
    int m0 = blockIdx.y * 128, n0 = blockIdx.x * 64;
    int row_a = Rm + rin + ((mat & 1) << 3);
    int row_b = rin + ((mat >> 1) << 3);

    float acc[8][4] = {};
    for (int k0 = 0; k0 < K; k0 += 64) {
        #pragma unroll
        for (int it = 0; it < 4; it++) {
            int idx = t + 256 * it;
            int r = idx >> 3, c = idx & 7;
            int gm = m0 + r;
            uint4 vh = make_uint4(0, 0, 0, 0), vl = vh;
            if (gm < M) {
                int am = aidx ? aidx[gm] : gm;
                if (a32) {
                    const float* Af = (const float*)A + (size_t)am * K + k0 + c * 8;
                    float4 v0 = *(const float4*)Af;
                    float4 v1 = *(const float4*)(Af + 4);
                    float vs[8] = { v0.x, v0.y, v0.z, v0.w, v1.x, v1.y, v1.z, v1.w };
                    __half hh[8], ll[8];
                    #pragma unroll
                    for (int q = 0; q < 8; q++) {
                        hh[q] = __float2half(vs[q]);
                        ll[q] = __float2half(vs[q] - __half2float(hh[q]));
                    }
                    vh = *(uint4*)hh;
                    vl = *(uint4*)ll;
                } else {
                    vh = *(const uint4*)&((const __half*)A)[(size_t)am * K + k0 + c * 8];
                    vl = *(const uint4*)&Al_[(size_t)am * K + k0 + c * 8];
                }
            }
            uint32_t off = (uint32_t)(r * 128 + ((c ^ (r & 7)) << 4));
            *(uint4*)(smc + SA_H + off) = vh;
            *(uint4*)(smc + SA_L + off) = vl;
        }
        #pragma unroll
        for (int it = 0; it < 2; it++) {
            int idx = t + 256 * it;
            int r = idx >> 3, c = idx & 7;
            int gn = n0 + r;
            uint4 vh = make_uint4(0, 0, 0, 0), vl = vh;
            if (gn < N) {
                vh = *(const uint4*)&Bh[gn * K + k0 + c * 8];
                vl = *(const uint4*)&Bl[gn * K + k0 + c * 8];
            }
            uint32_t off = (uint32_t)(r * 128 + ((c ^ (r & 7)) << 4));
            *(uint4*)(smc + SB_H + off) = vh;
            *(uint4*)(smc + SB_L + off) = vl;
        }
        __syncthreads();
        #pragma unroll
        for (int k16 = 0; k16 < 4; k16++) {
            uint32_t aH[4], aL[4];
            int ca = 2 * k16 + (mat >> 1);
            ldsm_x4(swz(sb + SA_H, row_a, ca, 8), aH[0], aH[1], aH[2], aH[3]);
            ldsm_x4(swz(sb + SA_L, row_a, ca, 8), aL[0], aL[1], aL[2], aL[3]);
            int cb = 2 * k16 + (mat & 1);
            uint32_t bH[4][4], bL[4][4];
            #pragma unroll
            for (int nh = 0; nh < 4; nh++) {
                ldsm_x4(swz(sb + SB_H, 16 * nh + row_b, cb, 8),
                        bH[nh][0], bH[nh][1], bH[nh][2], bH[nh][3]);
                ldsm_x4(swz(sb + SB_L, 16 * nh + row_b, cb, 8),
                        bL[nh][0], bL[nh][1], bL[nh][2], bL[nh][3]);
            }
            #pragma unroll
            for (int j = 0; j < 8; j++) {
                uint32_t h0 = bH[j >> 1][2 * (j & 1)], h1 = bH[j >> 1][2 * (j & 1) + 1];
                uint32_t l0 = bL[j >> 1][2 * (j & 1)], l1 = bL[j >> 1][2 * (j & 1) + 1];
                mma_fp16(acc[j], aH[0], aH[1], aH[2], aH[3], h0, h1);
                mma_fp16(acc[j], aL[0], aL[1], aL[2], aL[3], h0, h1);
                mma_fp16(acc[j], aH[0], aH[1], aH[2], aH[3], l0, l1);
            }
        }
        __syncthreads();
    }
    #pragma unroll
    for (int j = 0; j < 8; j++) {
        int gn = n0 + 8 * j + 2 * tg;
        if (gn < N) {
            float b0 = bias ? bias[gn] : 0.f;
            float b1 = bias ? bias[gn + 1] : 0.f;
            int gm0 = m0 + Rm + g;
            if (gm0 < M)
                *(float2*)&C[(size_t)gm0 * N + gn] = make_float2(acc[j][0] + b0, acc[j][1] + b1);
            if (gm0 + 8 < M)
                *(float2*)&C[(size_t)(gm0 + 8) * N + gn] = make_float2(acc[j][2] + b0, acc[j][3] + b1);
        }
    }
}

// ---------------- scalar GEMM (uc only) ----------------
__global__ void __launch_bounds__(256) k_gemm(const float* __restrict__ A,
                                              const float* __restrict__ Bw,
                                              float* __restrict__ C,
                                              int M, int N, int K) {
    __shared__ float As[64][33];
    __shared__ float Bs[64][33];
    int m0 = blockIdx.y * 64, n0 = blockIdx.x * 64;
    int tid = threadIdx.x;
    int tx = tid & 15, ty = tid >> 4;
    float acc[4][4] = {};
    for (int k0 = 0; k0 < K; k0 += 32) {
        #pragma unroll
        for (int i = 0; i < 2; i++) {
            int f = tid + 256 * i;
            int m = f >> 3, k4 = f & 7;
            int gm = m0 + m;
            float4 v = make_float4(0.f, 0.f, 0.f, 0.f);
            if (gm < M) v = *(const float4*)&A[gm * K + k0 + k4 * 4];
            As[m][k4 * 4 + 0] = v.x; As[m][k4 * 4 + 1] = v.y;
            As[m][k4 * 4 + 2] = v.z; As[m][k4 * 4 + 3] = v.w;
        }
        #pragma unroll
        for (int i = 0; i < 2; i++) {
            int f = tid + 256 * i;
            int n = f >> 3, k4 = f & 7;
            int gn = n0 + n;
            float4 v = make_float4(0.f, 0.f, 0.f, 0.f);
            if (gn < N) v = *(const float4*)&Bw[gn * K + k0 + k4 * 4];
            Bs[n][k4 * 4 + 0] = v.x; Bs[n][k4 * 4 + 1] = v.y;
            Bs[n][k4 * 4 + 2] = v.z; Bs[n][k4 * 4 + 3] = v.w;
        }
        __syncthreads();
        #pragma unroll
        for (int k = 0; k < 32; k++) {
            float a[4], b[4];
            #pragma unroll
            for (int r = 0; r < 4; r++) a[r] = As[ty * 4 + r][k];
            #pragma unroll
            for (int c = 0; c < 4; c++) b[c] = Bs[tx * 4 + c][k];
            #pragma unroll
            for (int r = 0; r < 4; r++)
                #pragma unroll
                for (int c = 0; c < 4; c++)
                    acc[r][c] += a[r] * b[c];
        }
        __syncthreads();
    }
    #pragma unroll
    for (int r = 0; r < 4; r++) {
        int gm = m0 + ty * 4 + r;
        if (gm < M) {
            #pragma unroll
            for (int c = 0; c < 4; c++) {
                int gn = n0 + tx * 4 + c;
                if (gn < N) C[gm * N + gn] = acc[r][c];
            }
        }
    }
}

// ---------------- final add ----------------
__global__ void k_add(float* __restrict__ out) {
    int i = blockIdx.x * blockDim.x + threadIdx.x;
    if (i < B * NC) out[i] += g_uc[i];
}

// ---------------- prop: inp = adj @ ao; writes fp16 [inp|h0] operand ----------------
#define PROP_SMEM ((L * L + L * 256) * 4)
__global__ void k_prop(const float* __restrict__ adj, const int* __restrict__ items,
                       const float* __restrict__ emb) {
    extern __shared__ float psm[];
    float* sA  = psm;
    float* sin = psm + L * L;
    int b = blockIdx.x, t = threadIdx.x;
    for (int i = t; i < L * L; i += 256) sA[i] = adj[b * L * L + i];
    for (int k = 0; k < L; k++) sin[k * 256 + t] = g_ao[(b * L + k) * 256 + t];
    __syncthreads();
    for (int l = 0; l < L; l++) {
        float acc = 0.f;
        #pragma unroll 10
        for (int k = 0; k < L; k++)
            acc += sA[l * L + k] * sin[k * 256 + t];
        __half h = __float2half(acc);
        g_Ah2[(b * L + l) * 384 + t] = h;
        g_Al2[(b * L + l) * 384 + t] = __float2half(acc - __half2float(h));
    }
    for (int i = t; i < L * H; i += 256) {
        int l = i >> 7, tt = i & 127;
        float v = emb[items[b * L + l] * H + tt];
        __half h = __float2half(v);
        g_Ah2[(b * L + l) * 384 + 256 + tt] = h;
        g_Al2[(b * L + l) * 384 + 256 + tt] = __float2half(v - __half2float(h));
    }
}

// ---------------- GRU elementwise + final fp16 splits ----------------
__global__ void k_gru_elem(const int* __restrict__ items, const int* __restrict__ lens,
                           const float* __restrict__ pos_emb) {
    int i = blockIdx.x * blockDim.x + threadIdx.x;
    int bl = i >> 7, t = i & 127;
    int b = bl / L, l = bl % L;
    const float* g = g_gates + bl * 512;
    float r = 1.f / (1.f + expf(-g[t]));
    float z = 1.f / (1.f + expf(-g[128 + t]));
    float n = tanhf(g[256 + t] + r * g[384 + t]);
    float h0 = __half2float(g_Ah2[bl * 384 + 256 + t]) + __half2float(g_Al2[bl * 384 + 256 + t]);
    float hn = n + z * (h0 - n);
    int item = items[bl];
    int len  = lens[b];
    int rev  = (item == 0) ? 0 : (len - 1 - l);
    float fin = fmaxf(g_sg[i], 0.f) + hn + pos_emb[rev * H + t];
    __half fh = __float2half(fin);
    __half fl = __float2half(fin - __half2float(fh));
    g_fh[(b * LP + l) * H + t] = fh;
    g_fl[(b * LP + l) * H + t] = fl;
    g_fch[i] = fh;
    g_fcl[i] = fl;
    if (l == len - 1) g_last[b * H + t] = fin;
}

// ---------------- candidate fp16 convert for tail ----------------
__global__ void k_cvt_cand() {
    int i = blockIdx.x * blockDim.x + threadIdx.x;   // NCP*H
    int n = i >> 7, k = i & 127;
    float vT = 0.f, vA = 0.f;
    if (n < NC) { vT = g_cTA[n * 256 + k]; vA = g_cTA[n * 256 + 128 + k]; }
    g_cTh[i] = __float2half(vT);
    g_cAh[i] = __float2half(vA);
}

// ---------------- attention readout -> g_u ----------------
#define ATTN_SMEM ((L * 2 * H + H + 8 * 64 + 3 * H) * 4 + 64 * 4)
__global__ void k_attn(const int* __restrict__ items,
                       const float* __restrict__ ipw, const float* __restrict__ ipb,
                       const float* __restrict__ opw, const float* __restrict__ opb,
                       const float* __restrict__ w3) {
    extern __shared__ float sm[];
    float* kvs = sm;
    float* qs  = kvs + L * 2 * H;
    float* att = qs + H;
    float* ctx = att + 8 * 64;
    float* sg  = ctx + H;
    float* ls  = sg + H;
    int*   its = (int*)(ls + H);

    int b = blockIdx.x, t = threadIdx.x;
    for (int i = t; i < L * 2 * H; i += 256) kvs[i] = g_kv[b * L * 2 * H + i];
    if (t < H) ls[t] = g_last[b * H + t];
    if (t < L) its[t] = items[b * L + t];
    __syncthreads();

    if (t < H) {
        float a = ipb[t];
        const float* w = ipw + t * H;
        #pragma unroll 8
        for (int k = 0; k < H; k++) a += ls[k] * w[k];
        qs[t] = a;
    }
    __syncthreads();
    for (int i = t; i < 8 * L; i += 256) {
        int hd = i / L, l = i % L;
        float a = 0.f;
        #pragma unroll
        for (int d = 0; d < 16; d++) a += qs[hd * 16 + d] * kvs[l * 2 * H + hd * 16 + d];
        att[hd * 64 + l] = (its[l] == 0) ? -INFINITY : a * 0.25f;
    }
    __syncthreads();
    if (t < 8) {
        float m = -INFINITY;
        for (int l = 0; l < L; l++) m = fmaxf(m, att[t * 64 + l]);
        float s = 0.f;
        for (int l = 0; l < L; l++) {
            float e = expf(att[t * 64 + l] - m);
            att[t * 64 + l] = e;
            s += e;
        }
        float inv = 1.f / s;
        for (int l = 0; l < L; l++) att[t * 64 + l] *= inv;
    }
    __syncthreads();
    if (t < H) {
        int hd = t / 16;
        float c = 0.f;
        for (int l = 0; l < L; l++) c += att[hd * 64 + l] * kvs[l * 2 * H + H + t];
        ctx[t] = c;
    }
    __syncthreads();
    if (t < H) {
        float a = opb[t];
        const float* w = opw + t * H;
        #pragma unroll 8
        for (int k = 0; k < H; k++) a += ctx[k] * w[k];
        sg[t] = a;
    }
    __syncthreads();
    if (t < H) {
        float u = 0.f;
        const float* w1 = w3 + t * 3 * H + H;
        const float* w2 = w3 + t * 3 * H + 2 * H;
        #pragma unroll 8
        for (int k = 0; k < H; k++) u += ls[k] * w1[k] + sg[k] * w2[k];
        g_u[b * H + t] = u;
    }
}

// ---------------- tail: 64-cand tile, warps split over l-halves, 3 CTA/SM ----------------
// smem: cT[64x128]=16K | cA=16K | F=[fh|fl][64x256]=32K | merge[2][3][64]=1.5K | its
#define T_CT   0
#define T_CA   16384
#define T_F    32768
#define T_MRG  65536
#define T_ITS  67072
#define TAIL_SMEM (T_ITS + 256)

__global__ void __launch_bounds__(256, 3) k_tail(const int* __restrict__ items,
                                                 float* __restrict__ out) {
    extern __shared__ char smc[];
    uint32_t sb = (uint32_t)__cvta_generic_to_shared(smc);
    float* mrg = (float*)(smc + T_MRG);    // [lh][{m,s,a}][64]
    int*   its = (int*)(smc + T_ITS);

    int n0 = blockIdx.x * 64;
    int bg = blockIdx.y * 8;
    int t  = threadIdx.x;
    int w  = t >> 5, lane = t & 31;
    int mat = lane >> 3, rin = lane & 7;
    int g = lane >> 2, tg = lane & 3;
    int rg = w >> 1;                      // row group 0..3 (rows 16rg..16rg+15)
    int lh = w & 1;                       // l-half (l in [32lh, 32lh+32))
    int Rm = 16 * rg;
    int row_a = Rm + rin + ((mat & 1) << 3);
    int row_b = rin + ((mat >> 1) << 3);

    // ---- load candidate tiles (64 rows x 16 chunks each) ----
    #pragma unroll
    for (int it = 0; it < 4; it++) {
        int idx = t + 256 * it;
        int r = idx >> 4, c = idx & 15;
        uint4 v = *(const uint4*)&g_cTh[(n0 + r) * H + c * 8];
        *(uint4*)(smc + T_CT + r * 256 + ((c ^ (r & 7)) << 4)) = v;
    }
    #pragma unroll
    for (int it = 0; it < 4; it++) {
        int idx = t + 256 * it;
        int r = idx >> 4, c = idx & 15;
        uint4 v = *(const uint4*)&g_cAh[(n0 + r) * H + c * 8];
        *(uint4*)(smc + T_CA + r * 256 + ((c ^ (r & 7)) << 4)) = v;
    }

    for (int bi = 0; bi < 8; bi++) {
        int b = bg + bi;
        // ---- load F = [fh|fl] ----
        #pragma unroll
        for (int it = 0; it < 8; it++) {
            int idx = t + 256 * it;
            int r = idx >> 5, c = idx & 31;
            const __half* src = (c < 16) ? &g_fh[(b * LP + r) * H + c * 8]
                                         : &g_fl[(b * LP + r) * H + (c - 16) * 8];
            uint4 v = *(const uint4*)src;
            *(uint4*)(smc + T_F + r * 512 + ((c ^ (r & 7)) << 4)) = v;
        }
        if (t < 64) its[t] = (t < L) ? items[b * L + t] : 0;
        __syncthreads();

        // ---- MMA mainloop: warp covers l in [32lh, 32lh+32), 4 j-tiles ----
        float Sacc[4][4] = {}, Gacc[4][4] = {};
        for (int kc = 0; kc < 8; kc++) {
            uint32_t aT[4], aA[4];
            int ch_a = 2 * kc + (mat >> 1);
            ldsm_x4(swz(sb + T_CT, row_a, ch_a, 16), aT[0], aT[1], aT[2], aT[3]);
            ldsm_x4(swz(sb + T_CA, row_a, ch_a, 16), aA[0], aA[1], aA[2], aA[3]);
            uint32_t bf[2][4];
            // fh half -> S and G
            #pragma unroll
            for (int nh2 = 0; nh2 < 2; nh2++) {
                int nh = 2 * lh + nh2;
                ldsm_x4(swz(sb + T_F, 16 * nh + row_b, 2 * kc + (mat & 1), 32),
                        bf[nh2][0], bf[nh2][1], bf[nh2][2], bf[nh2][3]);
            }
            #pragma unroll
            for (int jl = 0; jl < 4; jl++) {
                uint32_t b0 = bf[jl >> 1][2 * (jl & 1)], b1 = bf[jl >> 1][2 * (jl & 1) + 1];
                mma_fp16(Sacc[jl], aT[0], aT[1], aT[2], aT[3], b0, b1);
                mma_fp16(Gacc[jl], aA[0], aA[1], aA[2], aA[3], b0, b1);
            }
            // fl half -> G only
            #pragma unroll
            for (int nh2 = 0; nh2 < 2; nh2++) {
                int nh = 2 * lh + nh2;
                ldsm_x4(swz(sb + T_F, 16 * nh + row_b, 16 + 2 * kc + (mat & 1), 32),
                        bf[nh2][0], bf[nh2][1], bf[nh2][2], bf[nh2][3]);
            }
            #pragma unroll
            for (int jl = 0; jl < 4; jl++) {
                uint32_t b0 = bf[jl >> 1][2 * (jl & 1)], b1 = bf[jl >> 1][2 * (jl & 1) + 1];
                mma_fp16(Gacc[jl], aA[0], aA[1], aA[2], aA[3], b0, b1);
            }
        }

        // ---- per-warp masked softmax over its l-half ----
        unsigned mk0 = 0, mk1 = 0;
        #pragma unroll
        for (int jl = 0; jl < 4; jl++) {
            int lb = 32 * lh + 8 * jl + 2 * tg;
            if (its[lb] != 0)     mk0 |= (1u << jl);
            if (its[lb + 1] != 0) mk1 |= (1u << jl);
        }
        #pragma unroll
        for (int h = 0; h < 2; h++) {       // h=0: row Rm+g, h=1: row Rm+g+8
            float m = -INFINITY;
            #pragma unroll
            for (int jl = 0; jl < 4; jl++) {
                if (mk0 & (1u << jl)) m = fmaxf(m, Sacc[jl][2 * h]);
                if (mk1 & (1u << jl)) m = fmaxf(m, Sacc[jl][2 * h + 1]);
            }
            m = fmaxf(m, __shfl_xor_sync(0xFFFFFFFF, m, 1));
            m = fmaxf(m, __shfl_xor_sync(0xFFFFFFFF, m, 2));
            float s = 0.f, acc = 0.f;
            #pragma unroll
            for (int jl = 0; jl < 4; jl++) {
                if (mk0 & (1u << jl)) {
                    float e = __expf(Sacc[jl][2 * h] - m);
                    s += e; acc += e * Gacc[jl][2 * h];
                }
                if (mk1 & (1u << jl)) {
                    float e = __expf(Sacc[jl][2 * h + 1] - m);
                    s += e; acc += e * Gacc[jl][2 * h + 1];
                }
            }
            s   += __shfl_xor_sync(0xFFFFFFFF, s, 1);
            s   += __shfl_xor_sync(0xFFFFFFFF, s, 2);
            acc += __shfl_xor_sync(0xFFFFFFFF, acc, 1);
            acc += __shfl_xor_sync(0xFFFFFFFF, acc, 2);
            if (tg == 0) {
                int lr = Rm + g + 8 * h;    // local row 0..63
                mrg[lh * 192 + 0 * 64 + lr] = m;
                mrg[lh * 192 + 1 * 64 + lr] = s;
                mrg[lh * 192 + 2 * 64 + lr] = acc;
            }
        }
        __syncthreads();

        // ---- cross-half merge + write (64 threads) ----
        if (t < 64) {
            float m0 = mrg[0 * 192 + 0 * 64 + t], s0 = mrg[0 * 192 + 64 + t], a0 = mrg[0 * 192 + 128 + t];
            float m1 = mrg[1 * 192 + 0 * 64 + t], s1 = mrg[1 * 192 + 64 + t], a1 = mrg[1 * 192 + 128 + t];
            float nm = fmaxf(fmaxf(m0, m1), -1e30f);
            float e0 = __expf(m0 - nm), e1 = __expf(m1 - nm);
            float s = s0 * e0 + s1 * e1;
            float a = a0 * e0 + a1 * e1;
            int gn = n0 + t;
            if (gn < NC) out[b * NC + gn] = a / s;
        }
        __syncthreads();
    }
}

// ---------------- host launcher ----------------
extern "C" void kernel_launch(void* const* d_in, const int* in_sizes, int n_in,
                              void* d_out, int out_size) {
    const int*   items = (const int*)d_in[0];
    const int*   lens  = (const int*)d_in[1];
    const float* adj   = (const float*)d_in[2];
    const int*   erow  = (const int*)d_in[3];
    const int*   ecol  = (const int*)d_in[4];
    const float* ew    = (const float*)d_in[5];
    const float* emb   = (const float*)d_in[6];
    const float* pos   = (const float*)d_in[7];
    const float* gW    = (const float*)d_in[8];
    const float* gb    = (const float*)d_in[9];
    const float* liW   = (const float*)d_in[10];
    const float* lib   = (const float*)d_in[11];
    const float* loW   = (const float*)d_in[12];
    const float* lob   = (const float*)d_in[13];
    const float* w_ih  = (const float*)d_in[14];
    const float* w_hh  = (const float*)d_in[15];
    const float* b_ih  = (const float*)d_in[16];
    const float* b_hh  = (const float*)d_in[17];
    const float* ipw   = (const float*)d_in[18];
    const float* ipb   = (const float*)d_in[19];
    const float* opw   = (const float*)d_in[20];
    const float* opb   = (const float*)d_in[21];
    const float* wt    = (const float*)d_in[22];
    const float* w3    = (const float*)d_in[23];
    float* out = (float*)d_out;

    static bool s_init = false;
    static cudaStream_t s1, s2, s3;
    static cudaEvent_t evRoot, evCand, evGru, evGE, evUC, evPrep;
    if (!s_init) {
        cudaStreamCreateWithFlags(&s1, cudaStreamNonBlocking);
        cudaStreamCreateWithFlags(&s2, cudaStreamNonBlocking);
        cudaStreamCreateWithFlags(&s3, cudaStreamNonBlocking);
        cudaEventCreateWithFlags(&evRoot, cudaEventDisableTiming);
        cudaEventCreateWithFlags(&evCand, cudaEventDisableTiming);
        cudaEventCreateWithFlags(&evGru,  cudaEventDisableTiming);
        cudaEventCreateWithFlags(&evGE,   cudaEventDisableTiming);
        cudaEventCreateWithFlags(&evUC,   cudaEventDisableTiming);
        cudaEventCreateWithFlags(&evPrep, cudaEventDisableTiming);
        cudaFuncSetAttribute(k_attn, cudaFuncAttributeMaxDynamicSharedMemorySize, ATTN_SMEM);
        cudaFuncSetAttribute(k_tail, cudaFuncAttributeMaxDynamicSharedMemorySize, TAIL_SMEM);
        cudaFuncSetAttribute(k_prop, cudaFuncAttributeMaxDynamicSharedMemorySize, PROP_SMEM);
        cudaFuncSetAttribute(k_gemm16, cudaFuncAttributeMaxDynamicSharedMemorySize, G16_SMEM);
        s_init = true;
    }

    float* p_agg;   cudaGetSymbolAddress((void**)&p_agg,   g_agg);
    int*   p_mark;  cudaGetSymbolAddress((void**)&p_mark,  g_mark);
    float* p_sg;    cudaGetSymbolAddress((void**)&p_sg,    g_sg);
    float* p_ao;    cudaGetSymbolAddress((void**)&p_ao,    g_ao);
    float* p_gates; cudaGetSymbolAddress((void**)&p_gates, g_gates);
    float* p_kv;    cudaGetSymbolAddress((void**)&p_kv,    g_kv);
    float* p_u;     cudaGetSymbolAddress((void**)&p_u,     g_u);
    float* p_uc;    cudaGetSymbolAddress((void**)&p_uc,    g_uc);
    float* p_cTA;   cudaGetSymbolAddress((void**)&p_cTA,   g_cTA);
    float* p_bc;    cudaGetSymbolAddress((void**)&p_bc,    g_bc);
    float* p_bio;   cudaGetSymbolAddress((void**)&p_bio,   g_bio);
    __half *p_Ah2, *p_Al2, *p_fch, *p_fcl;
    __half *p_gWh, *p_gWl, *p_kvwh, *p_kvwl, *p_wcth, *p_wctl;
    __half *p_Wch, *p_Wcl, *p_Wioh, *p_Wiol;
    cudaGetSymbolAddress((void**)&p_Ah2, g_Ah2);   cudaGetSymbolAddress((void**)&p_Al2, g_Al2);
    cudaGetSymbolAddress((void**)&p_fch, g_fch);   cudaGetSymbolAddress((void**)&p_fcl, g_fcl);
    cudaGetSymbolAddress((void**)&p_gWh, g_gWh);   cudaGetSymbolAddress((void**)&p_gWl, g_gWl);
    cudaGetSymbolAddress((void**)&p_kvwh, g_kvwh); cudaGetSymbolAddress((void**)&p_kvwl, g_kvwl);
    cudaGetSymbolAddress((void**)&p_wcth, g_wcth); cudaGetSymbolAddress((void**)&p_wctl, g_wctl);
    cudaGetSymbolAddress((void**)&p_Wch, g_Wch);   cudaGetSymbolAddress((void**)&p_Wcl, g_Wcl);
    cudaGetSymbolAddress((void**)&p_Wioh, g_Wioh); cudaGetSymbolAddress((void**)&p_Wiol, g_Wiol);

    const int M = B * L;   // 3200

    cudaEventRecord(evRoot, 0);
    cudaStreamWaitEvent(s1, evRoot, 0);
    cudaStreamWaitEvent(s2, evRoot, 0);

    // ---- s1: candidate chain ----
    k_prep1<<<256, 128, 0, s1>>>(wt, w3);
    k_gemm16<<<dim3(4, (NC + 127) / 128), 256, G16_SMEM, s1>>>(
        emb + H, nullptr, p_wcth, p_wctl, (const float*)nullptr, p_cTA,
        NC, 256, H, 1, nullptr);
    k_cvt_cand<<<(NCP * H) / 256, 256, 0, s1>>>();
    cudaEventRecord(evCand, s1);

    // ---- s2: GRU chain ----
    k_prep2<<<1152, 384, 0, s2>>>(liW, lib, loW, lob, w_ih, w_hh, b_ih, b_hh,
                                  gW, ipw + H * H);
    cudaEventRecord(evPrep, s2);
    k_gemm16<<<dim3(4, 25), 256, G16_SMEM, s2>>>(
        emb, nullptr, p_Wioh, p_Wiol, p_bio, p_ao, M, 256, H, 1, items);
    k_prop<<<B, 256, PROP_SMEM, s2>>>(adj, items, emb);
    k_gemm16<<<dim3(8, 25), 256, G16_SMEM, s2>>>(
        p_Ah2, p_Al2, p_Wch, p_Wcl, p_bc, p_gates, M, 512, 384, 0, nullptr);
    cudaEventRecord(evGru, s2);

    // ---- s0: edge scatter + sg ----
    cudaMemsetAsync(p_agg, 0, NI * H * sizeof(float));
    cudaMemsetAsync(p_mark, 0, NI * sizeof(int));
    k_mark<<<(B * L + 255) / 256, 256>>>(items);
    k_edge<<<(E * 32 + 255) / 256, 256>>>(erow, ecol, ew, emb);
    cudaStreamWaitEvent(0, evPrep, 0);
    k_gemm16<<<dim3(2, 25), 256, G16_SMEM>>>(
        p_agg, nullptr, p_gWh, p_gWl, gb, p_sg, M, H, H, 1, items);

    cudaStreamWaitEvent(0, evGru, 0);
    k_gru_elem<<<(M * H) / 256, 256>>>(items, lens, pos);
    cudaEventRecord(evGE, 0);

    // ---- s3: attention branch + uc (concurrent with tail) ----
    cudaStreamWaitEvent(s3, evGE, 0);
    k_gemm16<<<dim3(4, 25), 256, G16_SMEM, s3>>>(
        p_fch, p_fcl, p_kvwh, p_kvwl, ipb + H, p_kv, M, 256, H, 0, nullptr);
    k_attn<<<B, 256, ATTN_SMEM, s3>>>(items, ipw, ipb, opw, opb, w3);
    k_gemm<<<dim3((NC + 63) / 64, 1), 256, 0, s3>>>(p_u, emb + H, p_uc, B, NC, H);
    cudaEventRecord(evUC, s3);

    // ---- s0: tail, then add ----
    cudaStreamWaitEvent(0, evCand, 0);
    k_tail<<<dim3(NCP / 64, B / 8), 256, TAIL_SMEM>>>(items, out);

    cudaStreamWaitEvent(0, evUC, 0);
    k_add<<<(B * NC + 255) / 256, 256>>>(out);
}